// round 13
// baseline (speedup 1.0000x reference)
#include <cuda_runtime.h>
#include <cuda_fp16.h>
#include <cstdint>

#define N        8192
#define D        192
#define BM       128
#define NB       64
#define NTILES   2080             // NB*(NB+1)/2
#define TILE_BYTES (BM * D * 2)   // 49152
#define NCTA     296              // 148 SM x 2 (all co-resident: barrier-safe)
#define QW       7                // NTILES / NCTA
#define REMW     8                // NTILES - NCTA*QW
#define CHUNKS   256              // 8192 rows / 32

// ---------------- device globals (zero-initialized at load) ----------------
__device__ double g_loss;
__device__ float  g_colacc[8][D];
__device__ float  g_sqacc[8];
__device__ int    g_pcount;
__device__ int    g_ready;
__device__ int    g_mcount;
__device__ float  g_sq[N];
__device__ float  g_c2;                 // log2(e)/(16*bw)
__device__ uint4  g_xh[N * D * 2 / 16]; // fp16 x, row stride 384B, 16B-group XOR swizzle

// ---------------- helpers ----------------
__device__ __forceinline__ uint32_t smem_u32(const void* p) {
    uint32_t a;
    asm("{ .reg .u64 t; cvta.to.shared.u64 t, %1; cvt.u32.u64 %0, t; }" : "=r"(a) : "l"(p));
    return a;
}
#define MBAR_INIT(a, c) asm volatile("mbarrier.init.shared.b64 [%0], %1;" :: "r"(a), "r"(c) : "memory")
#define MBAR_EXPECT_TX(a, b) asm volatile("mbarrier.arrive.expect_tx.shared.b64 _, [%0], %1;" :: "r"(a), "r"(b) : "memory")
#define MBAR_WAIT(a, ph) do { \
    uint32_t _m = (a), _p = (ph), _d; \
    asm volatile("{ .reg .pred p; mbarrier.try_wait.parity.acquire.cta.shared::cta.b64 p, [%1], %2; selp.b32 %0,1,0,p; }" \
        : "=r"(_d) : "r"(_m), "r"(_p) : "memory"); \
    if (!_d) { asm volatile("{ .reg .pred P1; WL_%=: mbarrier.try_wait.parity.acquire.cta.shared::cta.b64 P1, [%0], %1, 0x989680; @P1 bra.uni WD_%=; bra.uni WL_%=; WD_%=: }" \
        :: "r"(_m), "r"(_p) : "memory"); } } while (0)
__device__ __forceinline__ void bulk_g2s(uint32_t dst, const void* src, uint32_t bytes, uint32_t mbar) {
    asm volatile("cp.async.bulk.shared::cluster.global.mbarrier::complete_tx::bytes [%0], [%1], %2, [%3];"
        :: "r"(dst), "l"(src), "r"(bytes), "r"(mbar) : "memory");
}
#define LDSM_X4(r0, r1, r2, r3, a) \
    asm volatile("ldmatrix.sync.aligned.m8n8.x4.shared.b16 {%0,%1,%2,%3}, [%4];" \
        : "=r"(r0), "=r"(r1), "=r"(r2), "=r"(r3) : "r"(a))
#define MMA16816H(d, a, b0, b1) \
    asm volatile("mma.sync.aligned.m16n8k16.row.col.f16.f16.f16.f16 " \
        "{%0,%1},{%2,%3,%4,%5},{%6,%7},{%0,%1};" \
        : "+r"((d)[0]), "+r"((d)[1]) \
        : "r"((a)[0]), "r"((a)[1]), "r"((a)[2]), "r"((a)[3]), "r"(b0), "r"(b1))
__device__ __forceinline__ float ex2f(float x) {
    float r; asm("ex2.approx.ftz.f32 %0, %1;" : "=f"(r) : "f"(x)); return r;
}

// fused k-step: load A rows 0..63 (4 x4) + B once (2 x4), 16 MMAs
#define KSTEPF(KG) do { \
    uint32_t _a[4][4], _b[2][4]; \
    uint32_t _ga = (((uint32_t)(2*(KG)) + ahi) ^ swz) << 4; \
    uint32_t _gb = (((uint32_t)(2*(KG)) + bhi) ^ swz) << 4; \
    LDSM_X4(_a[0][0],_a[0][1],_a[0][2],_a[0][3], baseA + _ga); \
    LDSM_X4(_a[1][0],_a[1][1],_a[1][2],_a[1][3], baseA + 6144u + _ga); \
    LDSM_X4(_a[2][0],_a[2][1],_a[2][2],_a[2][3], baseA + 12288u + _ga); \
    LDSM_X4(_a[3][0],_a[3][1],_a[3][2],_a[3][3], baseA + 18432u + _ga); \
    LDSM_X4(_b[0][0],_b[0][1],_b[0][2],_b[0][3], baseB + _gb); \
    LDSM_X4(_b[1][0],_b[1][1],_b[1][2],_b[1][3], baseB + 6144u + _gb); \
    _Pragma("unroll") \
    for (int _fm = 0; _fm < 4; _fm++) { \
        MMA16816H(acc[_fm][0], _a[_fm], _b[0][0], _b[0][1]); \
        MMA16816H(acc[_fm][1], _a[_fm], _b[0][2], _b[0][3]); \
        MMA16816H(acc[_fm][2], _a[_fm], _b[1][0], _b[1][1]); \
        MMA16816H(acc[_fm][3], _a[_fm], _b[1][2], _b[1][3]); \
    } \
} while (0)

// epilogue of PREVIOUS tile's acc pair (4 elements) into parity buckets ta0/ta1
#define EPIP(FM, FN) do { \
    float2 _p0 = __half22float2(*(half2*)&pacc[FM][FN][0]); \
    float2 _p1 = __half22float2(*(half2*)&pacc[FM][FN][1]); \
    float _t, _t2, _t4, _t8; \
    _t = ex2f(fmaf(_p0.x, tc2, pnsi[(FM)*2]   + pnsj[(FN)*2]));   _t2=_t*_t; _t4=_t2*_t2; _t8=_t4*_t4; \
    ta0 += (fmaf(_t,_t,_t) + fmaf(_t4,_t4,_t4)) + _t8*_t8; \
    _t = ex2f(fmaf(_p0.y, tc2, pnsi[(FM)*2]   + pnsj[(FN)*2+1])); _t2=_t*_t; _t4=_t2*_t2; _t8=_t4*_t4; \
    ta1 += (fmaf(_t,_t,_t) + fmaf(_t4,_t4,_t4)) + _t8*_t8; \
    _t = ex2f(fmaf(_p1.x, tc2, pnsi[(FM)*2+1] + pnsj[(FN)*2]));   _t2=_t*_t; _t4=_t2*_t2; _t8=_t4*_t4; \
    ta0 += (fmaf(_t,_t,_t) + fmaf(_t4,_t4,_t4)) + _t8*_t8; \
    _t = ex2f(fmaf(_p1.y, tc2, pnsi[(FM)*2+1] + pnsj[(FN)*2+1])); _t2=_t*_t; _t4=_t2*_t2; _t8=_t4*_t4; \
    ta1 += (fmaf(_t,_t,_t) + fmaf(_t4,_t4,_t4)) + _t8*_t8; \
} while (0)

// ---------------- fused persistent kernel ----------------
#define OFF_A    0
#define OFF_B    49152
#define OFF_MBAR 98304
#define OFF_RED  98320
#define SMEM_DYN (98304 + 64 + 1024)

__global__ __launch_bounds__(256, 2) void k_all(const float* __restrict__ x,
                                                float* __restrict__ out) {
    extern __shared__ char dsm[];
    uint32_t sb = (smem_u32(dsm) + 1023u) & ~1023u;
    char* sp = dsm + (sb - smem_u32(dsm));

    int tid  = threadIdx.x;
    int wid  = tid >> 5, lane = tid & 31;
    int wM   = wid >> 2, wN = wid & 3;
    int gID  = lane >> 2, tig = lane & 3;
    int c    = blockIdx.x;

    __shared__ int s_go, s_win;

    // ================= phase 1: convert + reductions (CTAs 0..255) =================
    if (c < CHUNKS) {
        float* s_stage = (float*)sp;
        float* s_sq    = (float*)(sp + 24576);
        float* s_rowsq = (float*)(sp + 27648);

        #pragma unroll
        for (int it = 0; it < 3; it++) {
            int idx = tid + it * 256;
            int r = idx / 24, g = idx % 24;
            int gr = c * 32 + r;
            const float* src = x + (size_t)gr * D + g * 8;
            float4 f0 = *(const float4*)src;
            float4 f1 = *(const float4*)(src + 4);

            half2 hh[4];
            hh[0] = __float22half2_rn(make_float2(f0.x, f0.y));
            hh[1] = __float22half2_rn(make_float2(f0.z, f0.w));
            hh[2] = __float22half2_rn(make_float2(f1.x, f1.y));
            hh[3] = __float22half2_rn(make_float2(f1.z, f1.w));
            *(uint4*)((char*)g_xh + (size_t)gr * 384 +
                      (((uint32_t)g ^ (uint32_t)(gr & 7)) << 4)) = *(uint4*)hh;

            s_sq[r * 24 + g] = f0.x * f0.x + f0.y * f0.y + f0.z * f0.z + f0.w * f0.w
                             + f1.x * f1.x + f1.y * f1.y + f1.z * f1.z + f1.w * f1.w;
            float* sxp = &s_stage[r * D + g * 8];
            sxp[0] = f0.x; sxp[1] = f0.y; sxp[2] = f0.z; sxp[3] = f0.w;
            sxp[4] = f1.x; sxp[5] = f1.y; sxp[6] = f1.z; sxp[7] = f1.w;
        }
        __syncthreads();

        if (tid < 32) {
            float v = 0.f;
            #pragma unroll
            for (int k = 0; k < 24; k++) v += s_sq[tid * 24 + k];
            g_sq[c * 32 + tid] = v;
            s_rowsq[tid] = v;
        }
        if (tid >= 64) {
            int col = tid - 64;
            float cs = 0.f;
            #pragma unroll
            for (int r = 0; r < 32; r++) cs += s_stage[r * D + col];
            atomicAdd(&g_colacc[c & 7][col], cs);
        }
        __syncthreads();
        if (tid == 0) {
            float tot = 0.f;
            #pragma unroll
            for (int r = 0; r < 32; r++) tot += s_rowsq[r];
            atomicAdd(&g_sqacc[c & 7], tot);
        }
    }

    // ================= grid barrier + bandwidth constant =================
    __threadfence();
    __syncthreads();
    if (tid == 0) s_go = (atomicAdd(&g_pcount, 1) == NCTA - 1) ? 1 : 0;
    __syncthreads();
    if (s_go) {
        __threadfence();
        float* s_red2 = (float*)sp;
        float cs = 0.f;
        if (tid < D) {
            #pragma unroll
            for (int r = 0; r < 8; r++) cs += __ldcg(&g_colacc[r][tid]);
        }
        s_red2[tid] = cs * cs;
        __syncthreads();
        #pragma unroll
        for (int o = 128; o >= 32; o >>= 1) {
            if (tid < o) s_red2[tid] += s_red2[tid + o];
            __syncthreads();
        }
        if (tid < 32) {
            float v = s_red2[tid];
            #pragma unroll
            for (int o = 16; o > 0; o >>= 1) v += __shfl_down_sync(0xffffffffu, v, o);
            if (tid == 0) {
                float sumsq = 0.f;
                #pragma unroll
                for (int r = 0; r < 8; r++) sumsq += __ldcg(&g_sqacc[r]);
                double sumL2 = 2.0 * (double)N * (double)sumsq - 2.0 * (double)v;
                double bw = sumL2 / ((double)N * (double)N - (double)N);
                bw *= 0.25;
                g_c2 = (float)(1.4426950408889634 / (bw * 16.0));
                g_loss = 0.0;
                __threadfence();
                atomicExch(&g_ready, 1);
            }
        }
    }
    if (tid == 0) {
        volatile int* rp = &g_ready;
        while (*rp == 0) {}
    }
    __syncthreads();
    __threadfence();

    // ================= phase 2: pipelined HMMA tile loop =================
    int start = (c < REMW) ? c * (QW + 1) : REMW * (QW + 1) + (c - REMW) * QW;
    int count = (c < REMW) ? QW + 1 : QW;
    int bi = 0, s = start;
    while (s >= NB - bi) { s -= NB - bi; bi++; }
    int bj = bi + s;

    uint32_t mbar = sb + OFF_MBAR;
    if (tid == 0) MBAR_INIT(mbar, 1);
    __syncthreads();
    if (tid == 0) {
        MBAR_EXPECT_TX(mbar, 2 * TILE_BYTES);
        const char* xh = (const char*)g_xh;
        bulk_g2s(sb + OFF_A, xh + (size_t)bi * TILE_BYTES, TILE_BYTES, mbar);
        bulk_g2s(sb + OFF_B, xh + (size_t)bj * TILE_BYTES, TILE_BYTES, mbar);
    }

    uint32_t swz   = (uint32_t)(lane & 7);
    uint32_t ahi   = (uint32_t)(lane >> 4);
    uint32_t bhi   = (uint32_t)((lane >> 3) & 1);
    uint32_t baseA = sb + OFF_A + (uint32_t)(wM * 64 + (lane & 15)) * 384u;
    uint32_t baseB = sb + OFF_B + (uint32_t)(wN * 32 + ((lane >> 4) << 3) + (lane & 7)) * 384u;

    float c2 = __ldcg(&g_c2), tc2 = 2.f * c2, nc2 = -c2;

    float master = 0.f;
    int phase = 0;

    // previous-tile state (first iteration: weight 0, dummy epilogue self-cancels)
    uint32_t pacc[4][4][2];
    #pragma unroll
    for (int i = 0; i < 4; i++)
        #pragma unroll
        for (int j = 0; j < 4; j++) { pacc[i][j][0] = 0u; pacc[i][j][1] = 0u; }
    int   pbi = bi, pbj = bj;
    float pw = 0.f;

    for (int k = 0; k < count; k++) {
        // previous tile's row norms (same addresses as last iteration -> L1 hot)
        float pnsi[8], pnsj[8];
        #pragma unroll
        for (int fm = 0; fm < 4; fm++) {
            pnsi[fm * 2]     = nc2 * __ldg(&g_sq[pbi * BM + wM * 64 + fm * 16 + gID]);
            pnsi[fm * 2 + 1] = nc2 * __ldg(&g_sq[pbi * BM + wM * 64 + fm * 16 + gID + 8]);
        }
        #pragma unroll
        for (int fn = 0; fn < 4; fn++) {
            pnsj[fn * 2]     = nc2 * __ldg(&g_sq[pbj * BM + wN * 32 + fn * 8 + tig * 2]);
            pnsj[fn * 2 + 1] = nc2 * __ldg(&g_sq[pbj * BM + wN * 32 + fn * 8 + tig * 2 + 1]);
        }

        MBAR_WAIT(mbar, phase);
        phase ^= 1;

        float ta0 = 0.f, ta1 = 0.f;
        uint32_t acc[4][4][2];
        #pragma unroll
        for (int i = 0; i < 4; i++)
            #pragma unroll
            for (int j = 0; j < 4; j++) { acc[i][j][0] = 0u; acc[i][j][1] = 0u; }

        // ---- MMA of current tile with PREVIOUS tile's epilogue interleaved ----
        KSTEPF(0);  KSTEPF(1);
        EPIP(0,0);  KSTEPF(2);
        EPIP(0,1);  KSTEPF(3);
        EPIP(0,2);  KSTEPF(4);
        EPIP(0,3);  KSTEPF(5);
        EPIP(1,0);  KSTEPF(6);
        EPIP(1,1);  KSTEPF(7);
        EPIP(1,2);  KSTEPF(8);
        EPIP(1,3);  KSTEPF(9);
        EPIP(2,0);  KSTEPF(10);
        EPIP(2,1);  KSTEPF(11);
        EPIP(2,2);  EPIP(2,3);

        __syncthreads();   // all smem reads done -> safe to overwrite tiles

        int nbi = bi, nbj = bj + 1;
        if (nbj == NB) { nbi = bi + 1; nbj = nbi; }
        if (k + 1 < count && tid == 0) {
            uint32_t bytes = TILE_BYTES + ((nbi != bi) ? TILE_BYTES : 0);
            MBAR_EXPECT_TX(mbar, bytes);
            const char* xh = (const char*)g_xh;
            if (nbi != bi)
                bulk_g2s(sb + OFF_A, xh + (size_t)nbi * TILE_BYTES, TILE_BYTES, mbar);
            bulk_g2s(sb + OFF_B, xh + (size_t)nbj * TILE_BYTES, TILE_BYTES, mbar);
        }

        // remaining prev-epilogue (overlaps prefetch TMA)
        EPIP(3,0); EPIP(3,1); EPIP(3,2); EPIP(3,3);

        // fold previous tile; rotate state
        float tp = (gID & 1) ? (ta1 - ta0) : (ta0 - ta1);
        master += pw * tp;

        #pragma unroll
        for (int i = 0; i < 4; i++)
            #pragma unroll
            for (int j = 0; j < 4; j++) { pacc[i][j][0] = acc[i][j][0]; pacc[i][j][1] = acc[i][j][1]; }
        pbi = bi; pbj = bj;
        pw = (bi == bj) ? 1.f : 2.f;      // diag tiles self-count both orderings (+own diag)
        bi = nbi; bj = nbj;
    }

    // ---- tail epilogue for the last tile ----
    {
        float pnsi[8], pnsj[8];
        #pragma unroll
        for (int fm = 0; fm < 4; fm++) {
            pnsi[fm * 2]     = nc2 * __ldg(&g_sq[pbi * BM + wM * 64 + fm * 16 + gID]);
            pnsi[fm * 2 + 1] = nc2 * __ldg(&g_sq[pbi * BM + wM * 64 + fm * 16 + gID + 8]);
        }
        #pragma unroll
        for (int fn = 0; fn < 4; fn++) {
            pnsj[fn * 2]     = nc2 * __ldg(&g_sq[pbj * BM + wN * 32 + fn * 8 + tig * 2]);
            pnsj[fn * 2 + 1] = nc2 * __ldg(&g_sq[pbj * BM + wN * 32 + fn * 8 + tig * 2 + 1]);
        }
        float ta0 = 0.f, ta1 = 0.f;
        EPIP(0,0); EPIP(0,1); EPIP(0,2); EPIP(0,3);
        EPIP(1,0); EPIP(1,1); EPIP(1,2); EPIP(1,3);
        EPIP(2,0); EPIP(2,1); EPIP(2,2); EPIP(2,3);
        EPIP(3,0); EPIP(3,1); EPIP(3,2); EPIP(3,3);
        float tp = (gID & 1) ? (ta1 - ta0) : (ta0 - ta1);
        master += pw * tp;
    }

    float part = master;
    #pragma unroll
    for (int o = 16; o > 0; o >>= 1) part += __shfl_xor_sync(0xffffffffu, part, o);
    float* s_red = (float*)(sp + OFF_RED);
    if (lane == 0) s_red[wid] = part;
    __syncthreads();
    if (tid == 0) {
        float v = 0.f;
        #pragma unroll
        for (int w = 0; w < 8; w++) v += s_red[w];
        atomicAdd(&g_loss, (double)v);
    }

    // ================= finalization by last CTA (parallel state reset) =================
    __threadfence();
    __syncthreads();
    if (tid == 0) s_win = (atomicAdd(&g_mcount, 1) == NCTA - 1) ? 1 : 0;
    __syncthreads();
    if (s_win) {
        __threadfence();
        if (tid < D) {
            #pragma unroll
            for (int r = 0; r < 8; r++) g_colacc[r][tid] = 0.f;
        }
        if (tid < 8) g_sqacc[tid] = 0.f;
        __syncthreads();
        if (tid == 0) {
            double hn = (double)(N / 2);
            out[0] = (float)(g_loss / (hn * hn));   // diag tiles already include ~5N
            g_pcount = 0;
            g_ready  = 0;
            g_mcount = 0;
        }
    }
}

// ---------------- launch ----------------
extern "C" void kernel_launch(void* const* d_in, const int* in_sizes, int n_in,
                              void* d_out, int out_size) {
    const float* x = (const float*)d_in[0];
    float* out = (float*)d_out;

    cudaFuncSetAttribute(k_all, cudaFuncAttributeMaxDynamicSharedMemorySize, SMEM_DYN);
    k_all<<<NCTA, 256, SMEM_DYN>>>(x, out);
}

// round 14
// speedup vs baseline: 1.0418x; 1.0418x over previous
#include <cuda_runtime.h>
#include <cuda_fp16.h>
#include <cstdint>

#define N        8192
#define D        192
#define BM       128
#define NB       64
#define NTILES   2080             // NB*(NB+1)/2
#define TILE_BYTES (BM * D * 2)   // 49152
#define NCTA     296              // 148 SM x 2 (all co-resident: barrier-safe)
#define QW       7                // NTILES / NCTA
#define REMW     8                // NTILES - NCTA*QW
#define CHUNKS   256              // 8192 rows / 32

// ---------------- device globals (zero-initialized at load) ----------------
__device__ double g_loss;
__device__ float  g_colacc[8][D];
__device__ float  g_sqacc[8];
__device__ int    g_pcount;
__device__ int    g_ready;
__device__ int    g_mcount;
__device__ float  g_sq[N];
__device__ float  g_c2;                 // log2(e)/(16*bw)
__device__ uint4  g_xh[N * D * 2 / 16]; // fp16 x, row stride 384B, 16B-group XOR swizzle

// ---------------- helpers ----------------
__device__ __forceinline__ uint32_t smem_u32(const void* p) {
    uint32_t a;
    asm("{ .reg .u64 t; cvta.to.shared.u64 t, %1; cvt.u32.u64 %0, t; }" : "=r"(a) : "l"(p));
    return a;
}
#define MBAR_INIT(a, c) asm volatile("mbarrier.init.shared.b64 [%0], %1;" :: "r"(a), "r"(c) : "memory")
#define MBAR_EXPECT_TX(a, b) asm volatile("mbarrier.arrive.expect_tx.shared.b64 _, [%0], %1;" :: "r"(a), "r"(b) : "memory")
#define MBAR_WAIT(a, ph) do { \
    uint32_t _m = (a), _p = (ph), _d; \
    asm volatile("{ .reg .pred p; mbarrier.try_wait.parity.acquire.cta.shared::cta.b64 p, [%1], %2; selp.b32 %0,1,0,p; }" \
        : "=r"(_d) : "r"(_m), "r"(_p) : "memory"); \
    if (!_d) { asm volatile("{ .reg .pred P1; WL_%=: mbarrier.try_wait.parity.acquire.cta.shared::cta.b64 P1, [%0], %1, 0x989680; @P1 bra.uni WD_%=; bra.uni WL_%=; WD_%=: }" \
        :: "r"(_m), "r"(_p) : "memory"); } } while (0)
__device__ __forceinline__ void bulk_g2s(uint32_t dst, const void* src, uint32_t bytes, uint32_t mbar) {
    asm volatile("cp.async.bulk.shared::cluster.global.mbarrier::complete_tx::bytes [%0], [%1], %2, [%3];"
        :: "r"(dst), "l"(src), "r"(bytes), "r"(mbar) : "memory");
}
#define LDSM_X4(r0, r1, r2, r3, a) \
    asm volatile("ldmatrix.sync.aligned.m8n8.x4.shared.b16 {%0,%1,%2,%3}, [%4];" \
        : "=r"(r0), "=r"(r1), "=r"(r2), "=r"(r3) : "r"(a))
#define MMA16816H(d, a, b0, b1) \
    asm volatile("mma.sync.aligned.m16n8k16.row.col.f16.f16.f16.f16 " \
        "{%0,%1},{%2,%3,%4,%5},{%6,%7},{%0,%1};" \
        : "+r"((d)[0]), "+r"((d)[1]) \
        : "r"((a)[0]), "r"((a)[1]), "r"((a)[2]), "r"((a)[3]), "r"(b0), "r"(b1))
__device__ __forceinline__ float ex2f(float x) {
    float r; asm("ex2.approx.ftz.f32 %0, %1;" : "=f"(r) : "f"(x)); return r;
}

// load one k-step's fragments into buffer S: 4 A x4 (64 rows) + 2 B x4 (32 cols)
#define LDF(S, KG) do { \
    uint32_t _ga = (((uint32_t)(2*(KG)) + ahi) ^ swz) << 4; \
    uint32_t _gb = (((uint32_t)(2*(KG)) + bhi) ^ swz) << 4; \
    LDSM_X4(fa[S][0][0],fa[S][0][1],fa[S][0][2],fa[S][0][3], baseA + _ga); \
    LDSM_X4(fa[S][1][0],fa[S][1][1],fa[S][1][2],fa[S][1][3], baseA + 6144u + _ga); \
    LDSM_X4(fa[S][2][0],fa[S][2][1],fa[S][2][2],fa[S][2][3], baseA + 12288u + _ga); \
    LDSM_X4(fa[S][3][0],fa[S][3][1],fa[S][3][2],fa[S][3][3], baseA + 18432u + _ga); \
    LDSM_X4(fb[S][0][0],fb[S][0][1],fb[S][0][2],fb[S][0][3], baseB + _gb); \
    LDSM_X4(fb[S][1][0],fb[S][1][1],fb[S][1][2],fb[S][1][3], baseB + 6144u + _gb); \
} while (0)

// issue one k-step's 16 MMAs from buffer S
#define MMAF(S) do { \
    _Pragma("unroll") \
    for (int _fm = 0; _fm < 4; _fm++) { \
        MMA16816H(acc[_fm][0], fa[S][_fm], fb[S][0][0], fb[S][0][1]); \
        MMA16816H(acc[_fm][1], fa[S][_fm], fb[S][0][2], fb[S][0][3]); \
        MMA16816H(acc[_fm][2], fa[S][_fm], fb[S][1][0], fb[S][1][1]); \
        MMA16816H(acc[_fm][3], fa[S][_fm], fb[S][1][2], fb[S][1][3]); \
    } \
} while (0)

// epilogue of one acc pair (4 elements) into parity buckets ta0/ta1
#define EPIA(FM, FN) do { \
    float2 _p0 = __half22float2(*(half2*)&acc[FM][FN][0]); \
    float2 _p1 = __half22float2(*(half2*)&acc[FM][FN][1]); \
    float _t, _t2, _t4, _t8; \
    _t = ex2f(fmaf(_p0.x, tc2, nsi[(FM)*2]   + nsj[(FN)*2]));   _t2=_t*_t; _t4=_t2*_t2; _t8=_t4*_t4; \
    ta0 += (fmaf(_t,_t,_t) + fmaf(_t4,_t4,_t4)) + _t8*_t8; \
    _t = ex2f(fmaf(_p0.y, tc2, nsi[(FM)*2]   + nsj[(FN)*2+1])); _t2=_t*_t; _t4=_t2*_t2; _t8=_t4*_t4; \
    ta1 += (fmaf(_t,_t,_t) + fmaf(_t4,_t4,_t4)) + _t8*_t8; \
    _t = ex2f(fmaf(_p1.x, tc2, nsi[(FM)*2+1] + nsj[(FN)*2]));   _t2=_t*_t; _t4=_t2*_t2; _t8=_t4*_t4; \
    ta0 += (fmaf(_t,_t,_t) + fmaf(_t4,_t4,_t4)) + _t8*_t8; \
    _t = ex2f(fmaf(_p1.y, tc2, nsi[(FM)*2+1] + nsj[(FN)*2+1])); _t2=_t*_t; _t4=_t2*_t2; _t8=_t4*_t4; \
    ta1 += (fmaf(_t,_t,_t) + fmaf(_t4,_t4,_t4)) + _t8*_t8; \
} while (0)

// ---------------- fused persistent kernel ----------------
#define OFF_A    0
#define OFF_B    49152
#define OFF_MBAR 98304
#define OFF_RED  98320
#define SMEM_DYN (98304 + 64 + 1024)

__global__ __launch_bounds__(256, 2) void k_all(const float* __restrict__ x,
                                                float* __restrict__ out) {
    extern __shared__ char dsm[];
    uint32_t sb = (smem_u32(dsm) + 1023u) & ~1023u;
    char* sp = dsm + (sb - smem_u32(dsm));

    int tid  = threadIdx.x;
    int wid  = tid >> 5, lane = tid & 31;
    int wM   = wid >> 2, wN = wid & 3;
    int gID  = lane >> 2, tig = lane & 3;
    int c    = blockIdx.x;

    __shared__ int s_go, s_win;

    // ================= phase 1: convert + reductions (CTAs 0..255) =================
    if (c < CHUNKS) {
        float* s_stage = (float*)sp;
        float* s_sq    = (float*)(sp + 24576);
        float* s_rowsq = (float*)(sp + 27648);

        #pragma unroll
        for (int it = 0; it < 3; it++) {
            int idx = tid + it * 256;
            int r = idx / 24, g = idx % 24;
            int gr = c * 32 + r;
            const float* src = x + (size_t)gr * D + g * 8;
            float4 f0 = *(const float4*)src;
            float4 f1 = *(const float4*)(src + 4);

            half2 hh[4];
            hh[0] = __float22half2_rn(make_float2(f0.x, f0.y));
            hh[1] = __float22half2_rn(make_float2(f0.z, f0.w));
            hh[2] = __float22half2_rn(make_float2(f1.x, f1.y));
            hh[3] = __float22half2_rn(make_float2(f1.z, f1.w));
            *(uint4*)((char*)g_xh + (size_t)gr * 384 +
                      (((uint32_t)g ^ (uint32_t)(gr & 7)) << 4)) = *(uint4*)hh;

            s_sq[r * 24 + g] = f0.x * f0.x + f0.y * f0.y + f0.z * f0.z + f0.w * f0.w
                             + f1.x * f1.x + f1.y * f1.y + f1.z * f1.z + f1.w * f1.w;
            float* sxp = &s_stage[r * D + g * 8];
            sxp[0] = f0.x; sxp[1] = f0.y; sxp[2] = f0.z; sxp[3] = f0.w;
            sxp[4] = f1.x; sxp[5] = f1.y; sxp[6] = f1.z; sxp[7] = f1.w;
        }
        __syncthreads();

        if (tid < 32) {
            float v = 0.f;
            #pragma unroll
            for (int k = 0; k < 24; k++) v += s_sq[tid * 24 + k];
            g_sq[c * 32 + tid] = v;
            s_rowsq[tid] = v;
        }
        if (tid >= 64) {
            int col = tid - 64;
            float cs = 0.f;
            #pragma unroll
            for (int r = 0; r < 32; r++) cs += s_stage[r * D + col];
            atomicAdd(&g_colacc[c & 7][col], cs);
        }
        __syncthreads();
        if (tid == 0) {
            float tot = 0.f;
            #pragma unroll
            for (int r = 0; r < 32; r++) tot += s_rowsq[r];
            atomicAdd(&g_sqacc[c & 7], tot);
        }
    }

    // ================= grid barrier + bandwidth constant =================
    __threadfence();
    __syncthreads();
    if (tid == 0) s_go = (atomicAdd(&g_pcount, 1) == NCTA - 1) ? 1 : 0;
    __syncthreads();
    if (s_go) {
        __threadfence();
        float* s_red2 = (float*)sp;
        float cs = 0.f;
        if (tid < D) {
            #pragma unroll
            for (int r = 0; r < 8; r++) cs += __ldcg(&g_colacc[r][tid]);
        }
        s_red2[tid] = cs * cs;
        __syncthreads();
        #pragma unroll
        for (int o = 128; o >= 32; o >>= 1) {
            if (tid < o) s_red2[tid] += s_red2[tid + o];
            __syncthreads();
        }
        if (tid < 32) {
            float v = s_red2[tid];
            #pragma unroll
            for (int o = 16; o > 0; o >>= 1) v += __shfl_down_sync(0xffffffffu, v, o);
            if (tid == 0) {
                float sumsq = 0.f;
                #pragma unroll
                for (int r = 0; r < 8; r++) sumsq += __ldcg(&g_sqacc[r]);
                double sumL2 = 2.0 * (double)N * (double)sumsq - 2.0 * (double)v;
                double bw = sumL2 / ((double)N * (double)N - (double)N);
                bw *= 0.25;
                g_c2 = (float)(1.4426950408889634 / (bw * 16.0));
                g_loss = 0.0;
                __threadfence();
                atomicExch(&g_ready, 1);
            }
        }
    }
    if (tid == 0) {
        volatile int* rp = &g_ready;
        while (*rp == 0) {}
    }
    __syncthreads();
    __threadfence();

    // ================= phase 2: pipelined HMMA tile loop =================
    int start = (c < REMW) ? c * (QW + 1) : REMW * (QW + 1) + (c - REMW) * QW;
    int count = (c < REMW) ? QW + 1 : QW;
    int bi = 0, s = start;
    while (s >= NB - bi) { s -= NB - bi; bi++; }
    int bj = bi + s;

    uint32_t mbar = sb + OFF_MBAR;
    if (tid == 0) MBAR_INIT(mbar, 1);
    __syncthreads();
    if (tid == 0) {
        MBAR_EXPECT_TX(mbar, 2 * TILE_BYTES);
        const char* xh = (const char*)g_xh;
        bulk_g2s(sb + OFF_A, xh + (size_t)bi * TILE_BYTES, TILE_BYTES, mbar);
        bulk_g2s(sb + OFF_B, xh + (size_t)bj * TILE_BYTES, TILE_BYTES, mbar);
    }

    uint32_t swz   = (uint32_t)(lane & 7);
    uint32_t ahi   = (uint32_t)(lane >> 4);
    uint32_t bhi   = (uint32_t)((lane >> 3) & 1);
    uint32_t baseA = sb + OFF_A + (uint32_t)(wM * 64 + (lane & 15)) * 384u;
    uint32_t baseB = sb + OFF_B + (uint32_t)(wN * 32 + ((lane >> 4) << 3) + (lane & 7)) * 384u;

    float c2 = __ldcg(&g_c2), tc2 = 2.f * c2, nc2 = -c2;

    float master = 0.f;
    int phase = 0;

    for (int k = 0; k < count; k++) {
        bool diag = (bi == bj);
        float nsi[8], nsj[8];
        #pragma unroll
        for (int fm = 0; fm < 4; fm++) {
            nsi[fm * 2]     = nc2 * __ldg(&g_sq[bi * BM + wM * 64 + fm * 16 + gID]);
            nsi[fm * 2 + 1] = nc2 * __ldg(&g_sq[bi * BM + wM * 64 + fm * 16 + gID + 8]);
        }
        #pragma unroll
        for (int fn = 0; fn < 4; fn++) {
            nsj[fn * 2]     = nc2 * __ldg(&g_sq[bj * BM + wN * 32 + fn * 8 + tig * 2]);
            nsj[fn * 2 + 1] = nc2 * __ldg(&g_sq[bj * BM + wN * 32 + fn * 8 + tig * 2 + 1]);
        }

        MBAR_WAIT(mbar, phase);
        phase ^= 1;

        uint32_t acc[4][4][2];
        #pragma unroll
        for (int i = 0; i < 4; i++)
            #pragma unroll
            for (int j = 0; j < 4; j++) { acc[i][j][0] = 0u; acc[i][j][1] = 0u; }

        // ---- software-pipelined mainloop: load kg+1 BEFORE issuing kg's MMAs ----
        uint32_t fa[2][4][4], fb[2][2][4];
        LDF(0, 0);
        LDF(1, 1);  MMAF(0);
        LDF(0, 2);  MMAF(1);
        LDF(1, 3);  MMAF(0);
        LDF(0, 4);  MMAF(1);
        LDF(1, 5);  MMAF(0);
        LDF(0, 6);  MMAF(1);
        LDF(1, 7);  MMAF(0);
        LDF(0, 8);  MMAF(1);
        LDF(1, 9);  MMAF(0);
        LDF(0, 10); MMAF(1);
        LDF(1, 11); MMAF(0);
        MMAF(1);

        __syncthreads();   // all smem reads done -> safe to overwrite tiles

        int nbi = bi, nbj = bj + 1;
        if (nbj == NB) { nbi = bi + 1; nbj = nbi; }
        if (k + 1 < count && tid == 0) {
            uint32_t bytes = TILE_BYTES + ((nbi != bi) ? TILE_BYTES : 0);
            MBAR_EXPECT_TX(mbar, bytes);
            const char* xh = (const char*)g_xh;
            if (nbi != bi)
                bulk_g2s(sb + OFF_A, xh + (size_t)nbi * TILE_BYTES, TILE_BYTES, mbar);
            bulk_g2s(sb + OFF_B, xh + (size_t)nbj * TILE_BYTES, TILE_BYTES, mbar);
        }

        // ---- epilogue (registers only; overlaps async prefetch) ----
        float ta0 = 0.f, ta1 = 0.f;
        EPIA(0,0); EPIA(0,1); EPIA(0,2); EPIA(0,3);
        EPIA(1,0); EPIA(1,1); EPIA(1,2); EPIA(1,3);
        EPIA(2,0); EPIA(2,1); EPIA(2,2); EPIA(2,3);
        EPIA(3,0); EPIA(3,1); EPIA(3,2); EPIA(3,3);

        // diag tiles self-count both orderings (+own diagonal -> replaces +5N), weight 1
        float tp = (gID & 1) ? (ta1 - ta0) : (ta0 - ta1);
        master += diag ? tp : 2.f * tp;

        bi = nbi; bj = nbj;
    }

    float part = master;
    #pragma unroll
    for (int o = 16; o > 0; o >>= 1) part += __shfl_xor_sync(0xffffffffu, part, o);
    float* s_red = (float*)(sp + OFF_RED);
    if (lane == 0) s_red[wid] = part;
    __syncthreads();
    if (tid == 0) {
        float v = 0.f;
        #pragma unroll
        for (int w = 0; w < 8; w++) v += s_red[w];
        atomicAdd(&g_loss, (double)v);
    }

    // ================= finalization by last CTA (parallel state reset) =================
    __threadfence();
    __syncthreads();
    if (tid == 0) s_win = (atomicAdd(&g_mcount, 1) == NCTA - 1) ? 1 : 0;
    __syncthreads();
    if (s_win) {
        __threadfence();
        if (tid < D) {
            #pragma unroll
            for (int r = 0; r < 8; r++) g_colacc[r][tid] = 0.f;
        }
        if (tid < 8) g_sqacc[tid] = 0.f;
        __syncthreads();
        if (tid == 0) {
            double hn = (double)(N / 2);
            out[0] = (float)(g_loss / (hn * hn));   // diag tiles already include ~5N
            g_pcount = 0;
            g_ready  = 0;
            g_mcount = 0;
        }
    }
}

// ---------------- launch ----------------
extern "C" void kernel_launch(void* const* d_in, const int* in_sizes, int n_in,
                              void* d_out, int out_size) {
    const float* x = (const float*)d_in[0];
    float* out = (float*)d_out;

    cudaFuncSetAttribute(k_all, cudaFuncAttributeMaxDynamicSharedMemorySize, SMEM_DYN);
    k_all<<<NCTA, 256, SMEM_DYN>>>(x, out);
}